// round 4
// baseline (speedup 1.0000x reference)
#include <cuda_runtime.h>
#include <math.h>
#include <float.h>

// Chamfer distance, B=16, N=M=2048, D=4, fp32.
// ||x-y||^2 = cp - 2 p.q + cq (eps 1e-12 negligible at rel tol 1e-3).
// Main: per (batch, dir, point-chunk) block; 16 queries/thread packed as 8
// fma.rn.f32x2 operand sets; point chunk (64 pts) in SMEM duplicated-packed.
// Per j: 3 broadcast LDS + 32 fma2 + 16 FMNMX covering 32 pairs/thread.
// Scratch [PS][NQTOT]; combine: min over chunks, sqrt, deterministic sum.

#define BATCH    16
#define NP       2048
#define THREADS  128
#define QPT      16                          // queries per thread (8 packs)
#define NPACK    (QPT / 2)                   // 8
#define PS       32                          // point chunks
#define PTS      (NP / PS)                   // 64 points per chunk
#define NBLK     (BATCH * 2 * PS)            // 1024 blocks
#define NQTOT    (BATCH * 2 * NP)            // 65536 rows
#define CBLK     512
#define CTHR     128

__device__ float g_partmin[(size_t)PS * NQTOT];  // 8 MB
__device__ float g_psum[CBLK];
__device__ unsigned int g_count;                 // zero-init; self-resetting

// ---- packed f32x2 helpers -------------------------------------------------
__device__ __forceinline__ unsigned long long pk2(float lo, float hi) {
    unsigned long long r;
    asm("mov.b64 %0, {%1, %2};" : "=l"(r) : "f"(lo), "f"(hi));
    return r;
}
__device__ __forceinline__ void upk2(unsigned long long v, float& lo, float& hi) {
    asm("mov.b64 {%0, %1}, %2;" : "=f"(lo), "=f"(hi) : "l"(v));
}
__device__ __forceinline__ unsigned long long fma2(unsigned long long a,
                                                   unsigned long long b,
                                                   unsigned long long c) {
    unsigned long long d;
    asm("fma.rn.f32x2 %0, %1, %2, %3;" : "=l"(d) : "l"(a), "l"(b), "l"(c));
    return d;
}

// ---- main kernel ----------------------------------------------------------
extern "C" __global__ void __launch_bounds__(THREADS, 4)
chamfer_main(const float* __restrict__ x, const float* __restrict__ y)
{
    const int bid = blockIdx.x;
    const int pc  = bid & (PS - 1);
    const int dir = (bid >> 5) & 1;
    const int b   = bid >> 6;

    const float* qbase = (dir == 0 ? x : y) + (size_t)b * NP * 4;
    const float* pbase = (dir == 0 ? y : x) + (size_t)b * NP * 4;

    __shared__ float4 arrA[PTS];   // (-2p.x,-2p.x,-2p.y,-2p.y)
    __shared__ float4 arrB[PTS];   // (-2p.z,-2p.z,-2p.w,-2p.w)
    __shared__ float2 arrC[PTS];   // (cp, cp)

    const int tid = threadIdx.x;

    if (tid < PTS) {
        float4 p = ((const float4*)pbase)[pc * PTS + tid];
        float cp = p.x * p.x + p.y * p.y + p.z * p.z + p.w * p.w;
        arrA[tid] = make_float4(-2.f * p.x, -2.f * p.x, -2.f * p.y, -2.f * p.y);
        arrB[tid] = make_float4(-2.f * p.z, -2.f * p.z, -2.f * p.w, -2.f * p.w);
        arrC[tid] = make_float2(cp, cp);
    }

    // load 16 queries, pack pairwise (2p, 2p+1); cq recomputed in epilogue
    unsigned long long a0[NPACK], a1[NPACK], a2[NPACK], a3[NPACK];
#pragma unroll
    for (int p = 0; p < NPACK; p++) {
        float4 u = ((const float4*)qbase)[(2 * p)     * THREADS + tid];
        float4 v = ((const float4*)qbase)[(2 * p + 1) * THREADS + tid];
        a0[p] = pk2(u.x, v.x);
        a1[p] = pk2(u.y, v.y);
        a2[p] = pk2(u.z, v.z);
        a3[p] = pk2(u.w, v.w);
    }

    float m[QPT];
#pragma unroll
    for (int i = 0; i < QPT; i++) m[i] = FLT_MAX;

    __syncthreads();

    const ulonglong2* A = (const ulonglong2*)arrA;
    const ulonglong2* B = (const ulonglong2*)arrB;
    const unsigned long long* C = (const unsigned long long*)arrC;

#pragma unroll 4
    for (int j = 0; j < PTS; j++) {
        ulonglong2 va = A[j];            // broadcast LDS.128
        ulonglong2 vb = B[j];            // broadcast LDS.128
        unsigned long long vc = C[j];    // broadcast LDS.64
#pragma unroll
        for (int p = 0; p < NPACK; p++) {
            unsigned long long s = fma2(va.x, a0[p], vc);
            s = fma2(va.y, a1[p], s);
            s = fma2(vb.x, a2[p], s);
            s = fma2(vb.y, a3[p], s);
            float s0, s1;
            upk2(s, s0, s1);
            m[2*p]   = fminf(m[2*p],   s0);   // FMNMX -> alu pipe
            m[2*p+1] = fminf(m[2*p+1], s1);
        }
    }

    // epilogue: recompute cq from packs, fold in, coalesced store [pc][row]
    const int rowbase = (b * 2 + dir) * NP;
#pragma unroll
    for (int p = 0; p < NPACK; p++) {
        float x0, x1, y0, y1, z0, z1, w0, w1;
        upk2(a0[p], x0, x1);
        upk2(a1[p], y0, y1);
        upk2(a2[p], z0, z1);
        upk2(a3[p], w0, w1);
        float cq0 = x0*x0 + y0*y0 + z0*z0 + w0*w0;
        float cq1 = x1*x1 + y1*y1 + z1*z1 + w1*w1;
        int q0 = (2 * p)     * THREADS + tid;
        int q1 = (2 * p + 1) * THREADS + tid;
        g_partmin[(size_t)pc * NQTOT + rowbase + q0] = m[2*p]   + cq0;
        g_partmin[(size_t)pc * NQTOT + rowbase + q1] = m[2*p+1] + cq1;
    }
}

// ---- combine: min over chunks, sqrt, sum; last block finishes -------------
extern "C" __global__ void __launch_bounds__(CTHR)
chamfer_combine(float* __restrict__ out)
{
    const int qg = blockIdx.x * CTHR + threadIdx.x;   // 0..65535
    float mn = FLT_MAX;
#pragma unroll
    for (int pc = 0; pc < PS; pc++)
        mn = fminf(mn, g_partmin[(size_t)pc * NQTOT + qg]);  // coalesced LDG
    float d = sqrtf(fmaxf(mn, 0.f));

    __shared__ float red[CTHR];
    red[threadIdx.x] = d;
    __syncthreads();
#pragma unroll
    for (int s = CTHR / 2; s > 0; s >>= 1) {
        if (threadIdx.x < s) red[threadIdx.x] += red[threadIdx.x + s];
        __syncthreads();
    }

    __shared__ int is_last;
    if (threadIdx.x == 0) {
        g_psum[blockIdx.x] = red[0];
        __threadfence();
        unsigned int v = atomicAdd(&g_count, 1u);
        is_last = (v == CBLK - 1);
    }
    __syncthreads();

    if (is_last) {
        // deterministic: fixed 4-way serial fold per thread, then fixed tree
        int t = threadIdx.x;
        float v = g_psum[t] + g_psum[t + CTHR] + g_psum[t + 2*CTHR] + g_psum[t + 3*CTHR];
        red[t] = v;
        __syncthreads();
#pragma unroll
        for (int s = CTHR / 2; s > 0; s >>= 1) {
            if (t < s) red[t] += red[t + s];
            __syncthreads();
        }
        if (t == 0) {
            out[0] = red[0];
            __threadfence();
            g_count = 0;    // reset for graph replay
        }
    }
}

// ---- launch ---------------------------------------------------------------
extern "C" void kernel_launch(void* const* d_in, const int* in_sizes, int n_in,
                              void* d_out, int out_size)
{
    const float* x = (const float*)d_in[0];
    const float* y = (const float*)d_in[1];
    float* out = (float*)d_out;

    chamfer_main<<<NBLK, THREADS>>>(x, y);
    chamfer_combine<<<CBLK, CTHR>>>(out);
}